// round 5
// baseline (speedup 1.0000x reference)
#include <cuda_runtime.h>

#define B_ 32
#define S_ 2048
#define D_ 1024
#define E_ 64
#define K_ 8
#define T_ 128       // N_TAGS
#define NSPLIT 8
#define KCHUNK (D_ / NSPLIT)   // 128
#define BK 32
#define BM 32

// Scratch (allocation-free rule: __device__ globals)
__device__ float g_ent[B_ * E_ * D_];            // 8 MB pooled embeddings
__device__ float g_wt[D_ * T_];                  // 512 KB fc_w transposed [D][T]
__device__ float g_part[NSPLIT * B_ * E_ * T_];  // 8 MB k-split partials

// ---- packed f32x2 helpers (sm_103a) --------------------------------------
__device__ __forceinline__ unsigned long long pack2(float a) {
    unsigned long long r;
    asm("mov.b64 %0, {%1, %1};" : "=l"(r) : "f"(a));
    return r;
}
__device__ __forceinline__ void ffma2(unsigned long long& d,
                                      unsigned long long a,
                                      unsigned long long b) {
    asm("fma.rn.f32x2 %0, %1, %2, %3;" : "=l"(d) : "l"(a), "l"(b), "l"(d));
}

// ---------------------------------------------------------------------------
// Kernel P: gather + masked mean pool (R2-proven shape: 1 block per entity,
// 256 thr x float4). Blocks 0..127 additionally transpose one 32x32 tile of
// fc_w into g_wt -- hides the transpose under the pool's 2048 blocks.
// ---------------------------------------------------------------------------
__global__ __launch_bounds__(256) void pool_kernel(
    const float* __restrict__ hs,      // [B,S,D]
    const int*   __restrict__ idx,     // [B,E,K]
    const int*   __restrict__ counts,  // [B,E]
    const int*   __restrict__ nent,    // [B]
    const float* __restrict__ W)       // fc_w [T,D]
{
    __shared__ float tile[32][33];

    int be = blockIdx.x;           // 0..2047
    int b  = be >> 6;
    int e  = be & 63;
    int cnt = counts[be];
    bool active = (e < nent[b]);
    int t = threadIdx.x;

    float4 acc = make_float4(0.f, 0.f, 0.f, 0.f);
    if (active) {
        const float* base = hs + (size_t)b * (S_ * D_);
        #pragma unroll
        for (int k = 0; k < K_; ++k) {
            if (k < cnt) {
                int row = idx[be * K_ + k];
                float4 v = *(const float4*)(base + (size_t)row * D_ + t * 4);
                acc.x += v.x; acc.y += v.y; acc.z += v.z; acc.w += v.w;
            }
        }
        float inv = 1.0f / (float)cnt;
        acc.x *= inv; acc.y *= inv; acc.z *= inv; acc.w *= inv;
    }
    *(float4*)(g_ent + (size_t)be * D_ + t * 4) = acc;

    // --- fused fc_w transpose: first 128 blocks, one 32x32 tile each ---
    if (blockIdx.x < (D_ / 32) * (T_ / 32)) {
        int bx = blockIdx.x & 31;    // D tile index (0..31)
        int by = blockIdx.x >> 5;    // T tile index (0..3)
        int x  = t & 31;
        int y  = t >> 5;             // 0..7
        #pragma unroll
        for (int j = 0; j < 4; ++j)
            tile[y + j * 8][x] = W[(size_t)(by * 32 + y + j * 8) * D_ + bx * 32 + x];
        __syncthreads();
        #pragma unroll
        for (int j = 0; j < 4; ++j)
            g_wt[(size_t)(bx * 32 + y + j * 8) * T_ + by * 32 + x] = tile[x][y + j * 8];
    }
}

// ---------------------------------------------------------------------------
// Kernel B: k-split GEMM partials, register-prefetch pipelined.
// grid = (64 m-blocks, 8 k-splits) = 512 CTAs, block = 256 threads.
// BM=32, BN=128, BK=32; per-thread 2 rows x 8 cols via f32x2 FMA.
// ---------------------------------------------------------------------------
__global__ __launch_bounds__(256) void gemm_kernel()
{
    __shared__ __align__(16) float sA[BM][36];    // [row][k]
    __shared__ __align__(16) float sW[BK][132];   // [k][col]

    int tid   = threadIdx.x;
    int mblk  = blockIdx.x;
    int split = blockIdx.y;
    int row0  = (tid >> 4) * 2;        // 0..30
    int col0  = (tid & 15) * 8;        // 0..120
    int k0base = split * KCHUNK;

    // A-load mapping: 32 rows x 8 float4 = 256, one per thread
    int ar = tid >> 3;                 // 0..31
    int akq = tid & 7;                 // 0..7
    const float* aptr = g_ent + (size_t)(mblk * BM + ar) * D_ + k0base + akq * 4;

    unsigned long long acc[2][4];
    #pragma unroll
    for (int i = 0; i < 2; ++i)
        #pragma unroll
        for (int p = 0; p < 4; ++p) acc[i][p] = 0ULL;

    // prefetch tile 0
    float4 pa = *(const float4*)aptr;
    float4 pw[4];
    #pragma unroll
    for (int it = 0; it < 4; ++it) {
        int i2 = it * 256 + tid;
        int kr = i2 >> 5;
        int cq = i2 & 31;
        pw[it] = *(const float4*)(g_wt + (size_t)(k0base + kr) * T_ + cq * 4);
    }

    #pragma unroll
    for (int t4 = 0; t4 < KCHUNK / BK; ++t4) {
        // commit prefetched tile to smem
        *(float4*)&sA[ar][akq * 4] = pa;
        #pragma unroll
        for (int it = 0; it < 4; ++it) {
            int i2 = it * 256 + tid;
            int kr = i2 >> 5;
            int cq = i2 & 31;
            *(float4*)&sW[kr][cq * 4] = pw[it];
        }
        __syncthreads();

        // issue next tile's global loads (overlap with compute below)
        if (t4 < KCHUNK / BK - 1) {
            int k0n = k0base + (t4 + 1) * BK;
            pa = *(const float4*)(aptr + (t4 + 1) * BK);
            #pragma unroll
            for (int it = 0; it < 4; ++it) {
                int i2 = it * 256 + tid;
                int kr = i2 >> 5;
                int cq = i2 & 31;
                pw[it] = *(const float4*)(g_wt + (size_t)(k0n + kr) * T_ + cq * 4);
            }
        }

        #pragma unroll
        for (int g = 0; g < BK / 4; ++g) {
            float4 rA0 = *(const float4*)&sA[row0 + 0][g * 4];
            float4 rA1 = *(const float4*)&sA[row0 + 1][g * 4];
            #pragma unroll
            for (int j = 0; j < 4; ++j) {
                ulonglong2 w0 = *(const ulonglong2*)&sW[g * 4 + j][col0];
                ulonglong2 w1 = *(const ulonglong2*)&sW[g * 4 + j][col0 + 4];
                float a0 = (j == 0) ? rA0.x : (j == 1) ? rA0.y : (j == 2) ? rA0.z : rA0.w;
                float a1 = (j == 0) ? rA1.x : (j == 1) ? rA1.y : (j == 2) ? rA1.z : rA1.w;
                unsigned long long a20 = pack2(a0);
                unsigned long long a21 = pack2(a1);
                ffma2(acc[0][0], a20, w0.x);
                ffma2(acc[0][1], a20, w0.y);
                ffma2(acc[0][2], a20, w1.x);
                ffma2(acc[0][3], a20, w1.y);
                ffma2(acc[1][0], a21, w0.x);
                ffma2(acc[1][1], a21, w0.y);
                ffma2(acc[1][2], a21, w1.x);
                ffma2(acc[1][3], a21, w1.y);
            }
        }
        __syncthreads();
    }

    float* outp = g_part + (size_t)split * (B_ * E_ * T_);
    #pragma unroll
    for (int i = 0; i < 2; ++i) {
        ulonglong2 v0, v1;
        v0.x = acc[i][0]; v0.y = acc[i][1];
        v1.x = acc[i][2]; v1.y = acc[i][3];
        size_t base = (size_t)(mblk * BM + row0 + i) * T_ + col0;
        *(ulonglong2*)(outp + base)     = v0;
        *(ulonglong2*)(outp + base + 4) = v1;
    }
}

// ---------------------------------------------------------------------------
// Kernel R: reduce 8 partials + bias -> out. Scalar per thread, high occupancy.
// ---------------------------------------------------------------------------
__global__ __launch_bounds__(256) void reduce_kernel(
    const float* __restrict__ bias, float* __restrict__ out)
{
    int i = blockIdx.x * 256 + threadIdx.x;   // 0 .. 262143
    float s = bias[i & (T_ - 1)];
    #pragma unroll
    for (int sp = 0; sp < NSPLIT; ++sp)
        s += g_part[(size_t)sp * (B_ * E_ * T_) + i];
    out[i] = s;
}

// ---------------------------------------------------------------------------
extern "C" void kernel_launch(void* const* d_in, const int* in_sizes, int n_in,
                              void* d_out, int out_size)
{
    const float* hs     = (const float*)d_in[0];
    const int*   idx    = (const int*)  d_in[1];
    const int*   counts = (const int*)  d_in[2];
    const int*   nent   = (const int*)  d_in[3];
    const float* fcw    = (const float*)d_in[4];
    const float* fcb    = (const float*)d_in[5];
    float*       out    = (float*)d_out;

    pool_kernel<<<B_ * E_, 256>>>(hs, idx, counts, nent, fcw);
    gemm_kernel<<<dim3(B_ * E_ / BM, NSPLIT), 256>>>();
    reduce_kernel<<<(B_ * E_ * T_) / 256, 256>>>(fcb, out);
}

// round 6
// speedup vs baseline: 1.4058x; 1.4058x over previous
#include <cuda_runtime.h>

#define B_ 32
#define S_ 2048
#define D_ 1024
#define E_ 64
#define K_ 8
#define T_ 128       // N_TAGS
#define BK 32
#define BM 64
#define BN 32

// Scratch (allocation-free rule: __device__ globals)
__device__ float g_ent[B_ * E_ * D_];   // 8 MB pooled embeddings
__device__ float g_wt[D_ * T_];         // 512 KB fc_w transposed [D][T]

// ---- packed f32x2 helpers (sm_103a) --------------------------------------
__device__ __forceinline__ unsigned long long pack2(float a) {
    unsigned long long r;
    asm("mov.b64 %0, {%1, %1};" : "=l"(r) : "f"(a));
    return r;
}
__device__ __forceinline__ void ffma2(unsigned long long& d,
                                      unsigned long long a,
                                      unsigned long long b) {
    asm("fma.rn.f32x2 %0, %1, %2, %3;" : "=l"(d) : "l"(a), "l"(b), "l"(d));
}

// ---------------------------------------------------------------------------
// Kernel P: gather + masked mean pool (proven shape: 1 block/entity, 256 thr
// x float4). Blocks 0..127 additionally transpose one 32x32 tile of fc_w into
// g_wt (hidden under the 2048-block pool).
// ---------------------------------------------------------------------------
__global__ __launch_bounds__(256) void pool_kernel(
    const float* __restrict__ hs,      // [B,S,D]
    const int*   __restrict__ idx,     // [B,E,K]
    const int*   __restrict__ counts,  // [B,E]
    const int*   __restrict__ nent,    // [B]
    const float* __restrict__ W)       // fc_w [T,D]
{
    __shared__ float tile[32][33];

    int be = blockIdx.x;           // 0..2047
    int b  = be >> 6;
    int e  = be & 63;
    int cnt = counts[be];
    bool active = (e < nent[b]);
    int t = threadIdx.x;

    float4 acc = make_float4(0.f, 0.f, 0.f, 0.f);
    if (active) {
        const float* base = hs + (size_t)b * (S_ * D_);
        #pragma unroll
        for (int k = 0; k < K_; ++k) {
            if (k < cnt) {
                int row = idx[be * K_ + k];
                float4 v = *(const float4*)(base + (size_t)row * D_ + t * 4);
                acc.x += v.x; acc.y += v.y; acc.z += v.z; acc.w += v.w;
            }
        }
        float inv = 1.0f / (float)cnt;
        acc.x *= inv; acc.y *= inv; acc.z *= inv; acc.w *= inv;
    }
    *(float4*)(g_ent + (size_t)be * D_ + t * 4) = acc;

    // --- fused fc_w transpose: first 128 blocks, one 32x32 tile each ---
    if (blockIdx.x < (D_ / 32) * (T_ / 32)) {
        int bx = blockIdx.x & 31;    // D tile index
        int by = blockIdx.x >> 5;    // T tile index
        int x  = t & 31;
        int y  = t >> 5;             // 0..7
        #pragma unroll
        for (int j = 0; j < 4; ++j)
            tile[y + j * 8][x] = W[(size_t)(by * 32 + y + j * 8) * D_ + bx * 32 + x];
        __syncthreads();
        #pragma unroll
        for (int j = 0; j < 4; ++j)
            g_wt[(size_t)(bx * 32 + y + j * 8) * T_ + by * 32 + x] = tile[x][y + j * 8];
    }
}

// ---------------------------------------------------------------------------
// Kernel B: N-split GEMM, full K per CTA, direct output with bias.
// grid = (32 m-blocks, 4 n-blocks) = 128 CTAs (one wave), 256 threads.
// BM=64, BN=32, BK=32; per-thread 2 rows x 4 cols via f32x2 FMA.
// Register prefetch hides L2 latency of g_ent / g_wt.
// ---------------------------------------------------------------------------
__global__ __launch_bounds__(256) void gemm_kernel(
    const float* __restrict__ bias,    // [T]
    float*       __restrict__ out)     // [B*E, T]
{
    __shared__ __align__(16) float sA[BM][36];   // 9 KB
    __shared__ __align__(16) float sW[BK][36];   // 4.6 KB

    int tid  = threadIdx.x;
    int mblk = blockIdx.x;
    int nblk = blockIdx.y;
    int ncol0 = nblk * BN;

    int row0 = (tid >> 3) * 2;        // 0..62
    int col0 = (tid & 7) * 4;         // 0..28

    // A-load: 64 rows x 8 float4 = 512, 2 per thread
    int ar0 = tid >> 2;               // 0..63
    int aq0 = (tid & 3) * 2;          // float4 col 0,2,4,6
    const float* abase = g_ent + (size_t)(mblk * BM + ar0) * D_;
    // W-load: 32 k-rows x 8 float4 = 256, 1 per thread
    int wk = tid >> 3;                // 0..31
    int wq = tid & 7;                 // 0..7
    const float* wbase = g_wt + (size_t)wk * T_ + ncol0 + wq * 4;

    unsigned long long acc[2][2];
    acc[0][0] = acc[0][1] = acc[1][0] = acc[1][1] = 0ULL;

    // prefetch tile 0
    float4 pa0 = *(const float4*)(abase + aq0 * 4);
    float4 pa1 = *(const float4*)(abase + aq0 * 4 + 4);
    float4 pw  = *(const float4*)wbase;

    #pragma unroll 1
    for (int t4 = 0; t4 < D_ / BK; ++t4) {
        *(float4*)&sA[ar0][aq0 * 4]     = pa0;
        *(float4*)&sA[ar0][aq0 * 4 + 4] = pa1;
        *(float4*)&sW[wk][wq * 4]       = pw;
        __syncthreads();

        if (t4 < D_ / BK - 1) {
            int k0n = (t4 + 1) * BK;
            pa0 = *(const float4*)(abase + k0n + aq0 * 4);
            pa1 = *(const float4*)(abase + k0n + aq0 * 4 + 4);
            pw  = *(const float4*)(wbase + (size_t)k0n * T_);
        }

        #pragma unroll
        for (int g = 0; g < BK / 4; ++g) {
            float4 rA0 = *(const float4*)&sA[row0 + 0][g * 4];
            float4 rA1 = *(const float4*)&sA[row0 + 1][g * 4];
            #pragma unroll
            for (int j = 0; j < 4; ++j) {
                ulonglong2 w = *(const ulonglong2*)&sW[g * 4 + j][col0];
                float a0 = (j == 0) ? rA0.x : (j == 1) ? rA0.y : (j == 2) ? rA0.z : rA0.w;
                float a1 = (j == 0) ? rA1.x : (j == 1) ? rA1.y : (j == 2) ? rA1.z : rA1.w;
                unsigned long long a20 = pack2(a0);
                unsigned long long a21 = pack2(a1);
                ffma2(acc[0][0], a20, w.x);
                ffma2(acc[0][1], a20, w.y);
                ffma2(acc[1][0], a21, w.x);
                ffma2(acc[1][1], a21, w.y);
            }
        }
        __syncthreads();
    }

    // epilogue: unpack, add bias, store directly to out
    float4 bb = *(const float4*)(bias + ncol0 + col0);
    #pragma unroll
    for (int i = 0; i < 2; ++i) {
        float2 lo = *(float2*)&acc[i][0];
        float2 hi = *(float2*)&acc[i][1];
        float4 o;
        o.x = lo.x + bb.x; o.y = lo.y + bb.y;
        o.z = hi.x + bb.z; o.w = hi.y + bb.w;
        *(float4*)(out + (size_t)(mblk * BM + row0 + i) * T_ + ncol0 + col0) = o;
    }
}

// ---------------------------------------------------------------------------
extern "C" void kernel_launch(void* const* d_in, const int* in_sizes, int n_in,
                              void* d_out, int out_size)
{
    const float* hs     = (const float*)d_in[0];
    const int*   idx    = (const int*)  d_in[1];
    const int*   counts = (const int*)  d_in[2];
    const int*   nent   = (const int*)  d_in[3];
    const float* fcw    = (const float*)d_in[4];
    const float* fcb    = (const float*)d_in[5];
    float*       out    = (float*)d_out;

    pool_kernel<<<B_ * E_, 256>>>(hs, idx, counts, nent, fcw);
    gemm_kernel<<<dim3(B_ * E_ / BM, T_ / BN), 256>>>(fcb, out);
}

// round 7
// speedup vs baseline: 1.4331x; 1.0194x over previous
#include <cuda_runtime.h>

#define B_ 32
#define S_ 2048
#define D_ 1024
#define E_ 64
#define K_ 8
#define T_ 128       // N_TAGS
#define NSPLIT 8
#define KCHUNK (D_ / NSPLIT)   // 128
#define BK 16
#define BM 64

// Scratch (allocation-free rule: __device__ globals)
__device__ float g_ent[B_ * E_ * D_];            // 8 MB pooled embeddings
__device__ float g_wt[D_ * T_];                  // 512 KB fc_w transposed [D][T]
__device__ float g_part[NSPLIT * B_ * E_ * T_];  // 8 MB k-split partials

// ---- packed f32x2 helpers (sm_103a) --------------------------------------
__device__ __forceinline__ unsigned long long pack2(float a) {
    unsigned long long r;
    asm("mov.b64 %0, {%1, %1};" : "=l"(r) : "f"(a));
    return r;
}
__device__ __forceinline__ void ffma2(unsigned long long& d,
                                      unsigned long long a,
                                      unsigned long long b) {
    asm("fma.rn.f32x2 %0, %1, %2, %3;" : "=l"(d) : "l"(a), "l"(b), "l"(d));
}

// ---------------------------------------------------------------------------
// Kernel P: gather + masked mean pool (proven: 1 block/entity, 256 thr x
// float4). Blocks 0..127 also transpose one 32x32 tile of fc_w into g_wt.
// ---------------------------------------------------------------------------
__global__ __launch_bounds__(256) void pool_kernel(
    const float* __restrict__ hs,      // [B,S,D]
    const int*   __restrict__ idx,     // [B,E,K]
    const int*   __restrict__ counts,  // [B,E]
    const int*   __restrict__ nent,    // [B]
    const float* __restrict__ W)       // fc_w [T,D]
{
    __shared__ float tile[32][33];

    int be = blockIdx.x;           // 0..2047
    int b  = be >> 6;
    int e  = be & 63;
    int cnt = counts[be];
    bool active = (e < nent[b]);
    int t = threadIdx.x;

    float4 acc = make_float4(0.f, 0.f, 0.f, 0.f);
    if (active) {
        const float* base = hs + (size_t)b * (S_ * D_);
        #pragma unroll
        for (int k = 0; k < K_; ++k) {
            if (k < cnt) {
                int row = idx[be * K_ + k];
                float4 v = *(const float4*)(base + (size_t)row * D_ + t * 4);
                acc.x += v.x; acc.y += v.y; acc.z += v.z; acc.w += v.w;
            }
        }
        float inv = 1.0f / (float)cnt;
        acc.x *= inv; acc.y *= inv; acc.z *= inv; acc.w *= inv;
    }
    *(float4*)(g_ent + (size_t)be * D_ + t * 4) = acc;

    if (blockIdx.x < (D_ / 32) * (T_ / 32)) {
        int bx = blockIdx.x & 31;
        int by = blockIdx.x >> 5;
        int x  = t & 31;
        int y  = t >> 5;
        #pragma unroll
        for (int j = 0; j < 4; ++j)
            tile[y + j * 8][x] = W[(size_t)(by * 32 + y + j * 8) * D_ + bx * 32 + x];
        __syncthreads();
        #pragma unroll
        for (int j = 0; j < 4; ++j)
            g_wt[(size_t)(bx * 32 + y + j * 8) * T_ + by * 32 + x] = tile[x][y + j * 8];
    }
}

// ---------------------------------------------------------------------------
// Kernel B: k-split GEMM partials (R2-proven ratio, 2 CTAs/SM residency).
// grid = (32 m-blocks, 8 k-splits) = 256 CTAs, block = 256 threads.
// BM=64, BN=128, BK=16; per-thread 4 rows x 8 cols via f32x2 FMA.
// ---------------------------------------------------------------------------
__global__ __launch_bounds__(256, 2) void gemm_kernel()
{
    __shared__ __align__(16) float sA[BM][20];    // 5 KB  (16 k + pad)
    __shared__ __align__(16) float sW[BK][132];   // 8.25 KB

    int tid   = threadIdx.x;
    int mblk  = blockIdx.x;
    int split = blockIdx.y;
    int row0  = (tid >> 4) * 4;        // 0..60
    int col0  = (tid & 15) * 8;        // 0..120
    int k0base = split * KCHUNK;

    // A-load: 64 rows x 4 float4 = 256, one per thread
    int ar = tid >> 2;                 // 0..63
    int aq = tid & 3;                  // 0..3
    const float* abase = g_ent + (size_t)(mblk * BM + ar) * D_ + k0base + aq * 4;

    unsigned long long acc[4][4];
    #pragma unroll
    for (int i = 0; i < 4; ++i)
        #pragma unroll
        for (int p = 0; p < 4; ++p) acc[i][p] = 0ULL;

    // prefetch tile 0
    float4 pa = *(const float4*)abase;
    float4 pw[2];
    #pragma unroll
    for (int it = 0; it < 2; ++it) {
        int i2 = it * 256 + tid;
        int kr = i2 >> 5;              // 0..15
        int cq = i2 & 31;              // 0..31
        pw[it] = *(const float4*)(g_wt + (size_t)(k0base + kr) * T_ + cq * 4);
    }

    #pragma unroll 1
    for (int t16 = 0; t16 < KCHUNK / BK; ++t16) {
        // commit prefetched tile to smem
        *(float4*)&sA[ar][aq * 4] = pa;
        #pragma unroll
        for (int it = 0; it < 2; ++it) {
            int i2 = it * 256 + tid;
            int kr = i2 >> 5;
            int cq = i2 & 31;
            *(float4*)&sW[kr][cq * 4] = pw[it];
        }
        __syncthreads();

        // issue next tile's global loads (overlap with compute)
        if (t16 < KCHUNK / BK - 1) {
            int k0n = (t16 + 1) * BK;
            pa = *(const float4*)(abase + k0n);
            #pragma unroll
            for (int it = 0; it < 2; ++it) {
                int i2 = it * 256 + tid;
                int kr = i2 >> 5;
                int cq = i2 & 31;
                pw[it] = *(const float4*)(g_wt + (size_t)(k0base + k0n + kr) * T_ + cq * 4);
            }
        }

        #pragma unroll
        for (int g = 0; g < BK / 4; ++g) {
            float4 rA[4];
            #pragma unroll
            for (int i = 0; i < 4; ++i)
                rA[i] = *(const float4*)&sA[row0 + i][g * 4];

            #pragma unroll
            for (int j = 0; j < 4; ++j) {
                ulonglong2 w0 = *(const ulonglong2*)&sW[g * 4 + j][col0];
                ulonglong2 w1 = *(const ulonglong2*)&sW[g * 4 + j][col0 + 4];
                #pragma unroll
                for (int i = 0; i < 4; ++i) {
                    float aj = (j == 0) ? rA[i].x : (j == 1) ? rA[i].y
                             : (j == 2) ? rA[i].z : rA[i].w;
                    unsigned long long a2 = pack2(aj);
                    ffma2(acc[i][0], a2, w0.x);
                    ffma2(acc[i][1], a2, w0.y);
                    ffma2(acc[i][2], a2, w1.x);
                    ffma2(acc[i][3], a2, w1.y);
                }
            }
        }
        __syncthreads();
    }

    float* outp = g_part + (size_t)split * (B_ * E_ * T_);
    #pragma unroll
    for (int i = 0; i < 4; ++i) {
        ulonglong2 v0, v1;
        v0.x = acc[i][0]; v0.y = acc[i][1];
        v1.x = acc[i][2]; v1.y = acc[i][3];
        size_t base = (size_t)(mblk * BM + row0 + i) * T_ + col0;
        *(ulonglong2*)(outp + base)     = v0;
        *(ulonglong2*)(outp + base + 4) = v1;
    }
}

// ---------------------------------------------------------------------------
// Kernel R: reduce 8 partials + bias -> out. Scalar per thread, 1024 blocks.
// ---------------------------------------------------------------------------
__global__ __launch_bounds__(256) void reduce_kernel(
    const float* __restrict__ bias, float* __restrict__ out)
{
    int i = blockIdx.x * 256 + threadIdx.x;   // 0 .. 262143
    float s = bias[i & (T_ - 1)];
    #pragma unroll
    for (int sp = 0; sp < NSPLIT; ++sp)
        s += g_part[(size_t)sp * (B_ * E_ * T_) + i];
    out[i] = s;
}

// ---------------------------------------------------------------------------
extern "C" void kernel_launch(void* const* d_in, const int* in_sizes, int n_in,
                              void* d_out, int out_size)
{
    const float* hs     = (const float*)d_in[0];
    const int*   idx    = (const int*)  d_in[1];
    const int*   counts = (const int*)  d_in[2];
    const int*   nent   = (const int*)  d_in[3];
    const float* fcw    = (const float*)d_in[4];
    const float* fcb    = (const float*)d_in[5];
    float*       out    = (float*)d_out;

    pool_kernel<<<B_ * E_, 256>>>(hs, idx, counts, nent, fcw);
    gemm_kernel<<<dim3(B_ * E_ / BM, NSPLIT), 256>>>();
    reduce_kernel<<<(B_ * E_ * T_) / 256, 256>>>(fcb, out);
}

// round 9
// speedup vs baseline: 1.9821x; 1.3831x over previous
#include <cuda_runtime.h>
#include <cstdint>

#define B_ 32
#define S_ 2048
#define D_ 1024
#define E_ 64
#define K_ 8
#define T_ 128       // N_TAGS
#define KSPLIT 8
#define KCHUNK 128   // K per split
#define KS 32        // k sub-chunk staged in smem
#define STRIDE 36    // floats per smem row (conflict-free for ldmatrix)
#define ARR (128 * STRIDE)   // 4608 floats per tile array

// Scratch (allocation-free rule: __device__ globals)
__device__ float g_eh[B_ * E_ * D_];             // pooled, tf32-hi
__device__ float g_el[B_ * E_ * D_];             // pooled, tf32-lo
__device__ float g_wh[T_ * D_];                  // fc_w tf32-hi  [T][D]
__device__ float g_wl[T_ * D_];                  // fc_w tf32-lo  [T][D]
__device__ float g_part[KSPLIT * B_ * E_ * T_];  // k-split partials

// ---- tf32 round helper ----------------------------------------------------
__device__ __forceinline__ float tf32r(float x) {
    uint32_t u;
    asm("cvt.rna.tf32.f32 %0, %1;" : "=r"(u) : "f"(x));
    return __uint_as_float(u);
}

// ---- mma / ldmatrix wrappers (base-target PTX, sm_80+) ---------------------
__device__ __forceinline__ void ldsm4(uint32_t* r, uint32_t addr) {
    asm volatile("ldmatrix.sync.aligned.m8n8.x4.shared.b16 {%0,%1,%2,%3}, [%4];"
                 : "=r"(r[0]), "=r"(r[1]), "=r"(r[2]), "=r"(r[3]) : "r"(addr));
}
__device__ __forceinline__ void mma8(float* d, const uint32_t* a,
                                     uint32_t b0, uint32_t b1) {
    asm volatile(
        "mma.sync.aligned.m16n8k8.row.col.f32.tf32.tf32.f32 "
        "{%0,%1,%2,%3}, {%4,%5,%6,%7}, {%8,%9}, {%0,%1,%2,%3};"
        : "+f"(d[0]), "+f"(d[1]), "+f"(d[2]), "+f"(d[3])
        : "r"(a[0]), "r"(a[1]), "r"(a[2]), "r"(a[3]), "r"(b0), "r"(b1));
}

// ---------------------------------------------------------------------------
// Kernel P: gather + masked mean pool, writing tf32 hi/lo split.
// Blocks < 512 also split fc_w elementwise into g_wh/g_wl (keeps [T][D]).
// ---------------------------------------------------------------------------
__global__ __launch_bounds__(256) void pool_kernel(
    const float* __restrict__ hs,      // [B,S,D]
    const int*   __restrict__ idx,     // [B,E,K]
    const int*   __restrict__ counts,  // [B,E]
    const int*   __restrict__ nent,    // [B]
    const float* __restrict__ W)       // fc_w [T,D]
{
    int be = blockIdx.x;           // 0..2047
    int b  = be >> 6;
    int e  = be & 63;
    int cnt = counts[be];
    bool active = (e < nent[b]);
    int t = threadIdx.x;

    float4 acc = make_float4(0.f, 0.f, 0.f, 0.f);
    if (active) {
        const float* base = hs + (size_t)b * (S_ * D_);
        #pragma unroll
        for (int k = 0; k < K_; ++k) {
            if (k < cnt) {
                int row = idx[be * K_ + k];
                float4 v = *(const float4*)(base + (size_t)row * D_ + t * 4);
                acc.x += v.x; acc.y += v.y; acc.z += v.z; acc.w += v.w;
            }
        }
        float inv = 1.0f / (float)cnt;
        acc.x *= inv; acc.y *= inv; acc.z *= inv; acc.w *= inv;
    }
    float4 hi, lo;
    hi.x = tf32r(acc.x); lo.x = tf32r(acc.x - hi.x);
    hi.y = tf32r(acc.y); lo.y = tf32r(acc.y - hi.y);
    hi.z = tf32r(acc.z); lo.z = tf32r(acc.z - hi.z);
    hi.w = tf32r(acc.w); lo.w = tf32r(acc.w - hi.w);
    *(float4*)(g_eh + (size_t)be * D_ + t * 4) = hi;
    *(float4*)(g_el + (size_t)be * D_ + t * 4) = lo;

    if (blockIdx.x < (T_ * D_) / 256) {
        int i = blockIdx.x * 256 + t;
        float w = W[i];
        float wh = tf32r(w);
        g_wh[i] = wh;
        g_wl[i] = tf32r(w - wh);
    }
}

// ---------------------------------------------------------------------------
// Kernel B: tf32x3 split-K GEMM via mma.sync.m16n8k8 + ldmatrix + cp.async.
// grid = (16 m-tiles, 8 k-splits) = 128 CTAs, 256 threads (8 warps).
// CTA tile: M128 x N128 x K128; warp tile m32 x n64; double-buffered k32.
// ---------------------------------------------------------------------------
__global__ __launch_bounds__(256, 1) void mma_gemm()
{
    extern __shared__ float sm[];
    uint32_t smb;
    asm("{ .reg .u64 t; cvta.to.shared.u64 t, %1; cvt.u32.u64 %0, t; }"
        : "=r"(smb) : "l"(sm));

    int tid  = threadIdx.x;
    int lane = tid & 31;
    int warp = tid >> 5;
    int mi = warp >> 1;            // 0..3  -> m-sub (32 rows)
    int ni = warp & 1;             // 0..1  -> n-sub (64 cols)
    int mrow0 = blockIdx.x * 128;
    int split = blockIdx.y;
    int kbase = split * KCHUNK;

    // loader: 4 arrays {A_hi, A_lo, B_hi, B_lo}, each 128 rows x 32 floats
    const float* gb0 = g_eh + (size_t)mrow0 * D_;
    const float* gb1 = g_el + (size_t)mrow0 * D_;

    // ldmatrix per-lane offsets (floats)
    int tile = lane >> 3;
    int tr   = lane & 7;
    int rsel = (tile & 1) * 8;
    int csel = (tile >> 1) * 4;
    int aoff[2], boff[4];
    #pragma unroll
    for (int f = 0; f < 2; ++f)
        aoff[f] = (mi * 32 + f * 16 + rsel + tr) * STRIDE + csel;
    #pragma unroll
    for (int n2 = 0; n2 < 4; ++n2)
        boff[n2] = (ni * 64 + n2 * 16 + rsel + tr) * STRIDE + csel;

    float acc[2][8][4];
    #pragma unroll
    for (int f = 0; f < 2; ++f)
        #pragma unroll
        for (int n = 0; n < 8; ++n)
            #pragma unroll
            for (int p = 0; p < 4; ++p) acc[f][n][p] = 0.f;

    // issue cp.async stage loads for sub-chunk `it` into stage buffer `stg`
    auto issue = [&](int stg, int it) {
        int kc = kbase + it * KS;
        #pragma unroll
        for (int a = 0; a < 4; ++a) {
            const float* gsrc = (a == 0) ? gb0 : (a == 1) ? gb1
                              : (a == 2) ? g_wh : g_wl;
            #pragma unroll
            for (int j = 0; j < 4; ++j) {
                int i   = tid + j * 256;
                int row = i >> 3;
                int q   = i & 7;
                uint32_t dst = smb + (uint32_t)(((stg * 4 + a) * ARR + row * STRIDE + q * 4) * 4);
                const float* src = gsrc + (size_t)row * D_ + kc + q * 4;
                asm volatile("cp.async.cg.shared.global [%0], [%1], 16;"
                             :: "r"(dst), "l"(src) : "memory");
            }
        }
        asm volatile("cp.async.commit_group;" ::: "memory");
    };

    issue(0, 0);

    #pragma unroll 1
    for (int it = 0; it < KCHUNK / KS; ++it) {
        int s = it & 1;
        asm volatile("cp.async.wait_group 0;" ::: "memory");
        __syncthreads();
        if (it + 1 < KCHUNK / KS) issue((it + 1) & 1, it + 1);

        uint32_t baseAh = smb + (uint32_t)((s * 4 + 0) * ARR * 4);
        uint32_t baseAl = smb + (uint32_t)((s * 4 + 1) * ARR * 4);
        uint32_t baseBh = smb + (uint32_t)((s * 4 + 2) * ARR * 4);
        uint32_t baseBl = smb + (uint32_t)((s * 4 + 3) * ARR * 4);

        #pragma unroll
        for (int ks = 0; ks < KS / 8; ++ks) {
            uint32_t aH[2][4], aL[2][4];
            #pragma unroll
            for (int f = 0; f < 2; ++f) {
                ldsm4(aH[f], baseAh + (uint32_t)((aoff[f] + ks * 8) * 4));
                ldsm4(aL[f], baseAl + (uint32_t)((aoff[f] + ks * 8) * 4));
            }
            #pragma unroll
            for (int n2 = 0; n2 < 4; ++n2) {
                uint32_t bH[4];
                ldsm4(bH, baseBh + (uint32_t)((boff[n2] + ks * 8) * 4));
                #pragma unroll
                for (int f = 0; f < 2; ++f) {
                    mma8(acc[f][n2 * 2 + 0], aH[f], bH[0], bH[2]);
                    mma8(acc[f][n2 * 2 + 1], aH[f], bH[1], bH[3]);
                    mma8(acc[f][n2 * 2 + 0], aL[f], bH[0], bH[2]);
                    mma8(acc[f][n2 * 2 + 1], aL[f], bH[1], bH[3]);
                }
                uint32_t bL[4];
                ldsm4(bL, baseBl + (uint32_t)((boff[n2] + ks * 8) * 4));
                #pragma unroll
                for (int f = 0; f < 2; ++f) {
                    mma8(acc[f][n2 * 2 + 0], aH[f], bL[0], bL[2]);
                    mma8(acc[f][n2 * 2 + 1], aH[f], bL[1], bL[3]);
                }
            }
        }
        __syncthreads();
    }

    // epilogue: write partials
    float* op = g_part + (size_t)split * (B_ * E_ * T_);
    #pragma unroll
    for (int f = 0; f < 2; ++f) {
        int r0 = mrow0 + mi * 32 + f * 16 + (lane >> 2);
        #pragma unroll
        for (int nt = 0; nt < 8; ++nt) {
            int c = ni * 64 + nt * 8 + (lane & 3) * 2;
            float2 v0 = make_float2(acc[f][nt][0], acc[f][nt][1]);
            float2 v1 = make_float2(acc[f][nt][2], acc[f][nt][3]);
            *(float2*)(op + (size_t)r0 * T_ + c)       = v0;
            *(float2*)(op + (size_t)(r0 + 8) * T_ + c) = v1;
        }
    }
}

// ---------------------------------------------------------------------------
// Kernel R: reduce 8 partials + bias -> out.
// ---------------------------------------------------------------------------
__global__ __launch_bounds__(256) void reduce_kernel(
    const float* __restrict__ bias, float* __restrict__ out)
{
    int i = blockIdx.x * 256 + threadIdx.x;   // 0 .. 262143
    float s = bias[i & (T_ - 1)];
    #pragma unroll
    for (int sp = 0; sp < KSPLIT; ++sp)
        s += g_part[(size_t)sp * (B_ * E_ * T_) + i];
    out[i] = s;
}

// ---------------------------------------------------------------------------
extern "C" void kernel_launch(void* const* d_in, const int* in_sizes, int n_in,
                              void* d_out, int out_size)
{
    const float* hs     = (const float*)d_in[0];
    const int*   idx    = (const int*)  d_in[1];
    const int*   counts = (const int*)  d_in[2];
    const int*   nent   = (const int*)  d_in[3];
    const float* fcw    = (const float*)d_in[4];
    const float* fcb    = (const float*)d_in[5];
    float*       out    = (float*)d_out;

    const int smem_bytes = 2 * 4 * ARR * 4;   // 147456
    cudaFuncSetAttribute(mma_gemm, cudaFuncAttributeMaxDynamicSharedMemorySize,
                         smem_bytes);

    pool_kernel<<<B_ * E_, 256>>>(hs, idx, counts, nent, fcw);
    mma_gemm<<<dim3(B_ * E_ / 128, KSPLIT), 256, smem_bytes>>>();
    reduce_kernel<<<(B_ * E_ * T_) / 256, 256>>>(fcb, out);
}

// round 10
// speedup vs baseline: 2.1586x; 1.0890x over previous
#include <cuda_runtime.h>
#include <cstdint>

#define B_ 32
#define S_ 2048
#define D_ 1024
#define E_ 64
#define K_ 8
#define T_ 128       // N_TAGS
#define KSPLIT 8
#define KCHUNK 128   // K per split
#define KS 32        // k sub-chunk staged in smem
#define STRIDE 36    // floats per smem row (conflict-free ldmatrix, 16B aligned)
#define A_SZ (64 * STRIDE)    // A tile floats per stage (M=64)
#define B_SZ (128 * STRIDE)   // B tile floats per stage (N=128)
#define STG  (A_SZ + B_SZ)

// Scratch (allocation-free rule: __device__ globals)
__device__ float g_ent[B_ * E_ * D_];            // 8 MB pooled embeddings (fp32)
__device__ float g_part[KSPLIT * B_ * E_ * T_];  // 8 MB k-split partials

// ---- tf32 round helper ----------------------------------------------------
__device__ __forceinline__ uint32_t tf32r(float x) {
    uint32_t u;
    asm("cvt.rna.tf32.f32 %0, %1;" : "=r"(u) : "f"(x));
    return u;
}
// split one fp32 fragment register into tf32 hi/lo
__device__ __forceinline__ void split2(uint32_t v, uint32_t& h, uint32_t& l) {
    float f = __uint_as_float(v);
    h = tf32r(f);
    l = tf32r(f - __uint_as_float(h));
}

// ---- mma / ldmatrix wrappers (base-target PTX, sm_80+) ---------------------
__device__ __forceinline__ void ldsm4(uint32_t* r, uint32_t addr) {
    asm volatile("ldmatrix.sync.aligned.m8n8.x4.shared.b16 {%0,%1,%2,%3}, [%4];"
                 : "=r"(r[0]), "=r"(r[1]), "=r"(r[2]), "=r"(r[3]) : "r"(addr));
}
__device__ __forceinline__ void mma8(float* d, const uint32_t* a,
                                     uint32_t b0, uint32_t b1) {
    asm volatile(
        "mma.sync.aligned.m16n8k8.row.col.f32.tf32.tf32.f32 "
        "{%0,%1,%2,%3}, {%4,%5,%6,%7}, {%8,%9}, {%0,%1,%2,%3};"
        : "+f"(d[0]), "+f"(d[1]), "+f"(d[2]), "+f"(d[3])
        : "r"(a[0]), "r"(a[1]), "r"(a[2]), "r"(a[3]), "r"(b0), "r"(b1));
}

// ---------------------------------------------------------------------------
// Kernel P: gather + masked mean pool (proven: 1 block/entity, 256 thr x
// float4, plain fp32 output). No weight preprocessing needed this round.
// ---------------------------------------------------------------------------
__global__ __launch_bounds__(256) void pool_kernel(
    const float* __restrict__ hs,      // [B,S,D]
    const int*   __restrict__ idx,     // [B,E,K]
    const int*   __restrict__ counts,  // [B,E]
    const int*   __restrict__ nent)    // [B]
{
    int be = blockIdx.x;           // 0..2047
    int b  = be >> 6;
    int e  = be & 63;
    int cnt = counts[be];
    bool active = (e < nent[b]);
    int t = threadIdx.x;

    float4 acc = make_float4(0.f, 0.f, 0.f, 0.f);
    if (active) {
        const float* base = hs + (size_t)b * (S_ * D_);
        #pragma unroll
        for (int k = 0; k < K_; ++k) {
            if (k < cnt) {
                int row = idx[be * K_ + k];
                float4 v = *(const float4*)(base + (size_t)row * D_ + t * 4);
                acc.x += v.x; acc.y += v.y; acc.z += v.z; acc.w += v.w;
            }
        }
        float inv = 1.0f / (float)cnt;
        acc.x *= inv; acc.y *= inv; acc.z *= inv; acc.w *= inv;
    }
    *(float4*)(g_ent + (size_t)be * D_ + t * 4) = acc;
}

// ---------------------------------------------------------------------------
// Kernel B: tf32x3 split-K GEMM, register-space hi/lo split.
// grid = (32 m-tiles, 8 k-splits) = 256 CTAs (2/SM), 256 threads (8 warps).
// CTA tile: M64 x N128 x K128; warp tile m32 x n32; double-buffered k32.
// A from g_ent (fp32), B from fc_w[T,D] directly (fp32) -> split after ldsm.
// ---------------------------------------------------------------------------
__global__ __launch_bounds__(256, 2) void mma_gemm(const float* __restrict__ fcw)
{
    extern __shared__ float sm[];
    uint32_t smb;
    asm("{ .reg .u64 t; cvta.to.shared.u64 t, %1; cvt.u32.u64 %0, t; }"
        : "=r"(smb) : "l"(sm));

    int tid  = threadIdx.x;
    int lane = tid & 31;
    int warp = tid >> 5;
    int mi = warp >> 2;            // 0..1  -> m-sub (32 rows)
    int ni = warp & 3;             // 0..3  -> n-sub (32 cols)
    int mrow0 = blockIdx.x * 64;
    int split = blockIdx.y;
    int kbase = split * KCHUNK;

    // ldmatrix per-lane offsets (floats, within tile arrays)
    int tile = lane >> 3;
    int tr   = lane & 7;
    int rsel = (tile & 1) * 8;
    int csel = (tile >> 1) * 4;
    int aoff[2], boff[2];
    #pragma unroll
    for (int f = 0; f < 2; ++f)
        aoff[f] = (mi * 32 + f * 16 + rsel + tr) * STRIDE + csel;
    #pragma unroll
    for (int n2 = 0; n2 < 2; ++n2)
        boff[n2] = (ni * 32 + n2 * 16 + rsel + tr) * STRIDE + csel;

    float acc[2][4][4];
    #pragma unroll
    for (int f = 0; f < 2; ++f)
        #pragma unroll
        for (int n = 0; n < 4; ++n)
            #pragma unroll
            for (int p = 0; p < 4; ++p) acc[f][n][p] = 0.f;

    // issue cp.async stage loads for sub-chunk `it` into stage buffer `stg`
    auto issue = [&](int stg, int it) {
        int kc = kbase + it * KS;
        // A: 64 rows x 8 float4 = 512
        #pragma unroll
        for (int j = 0; j < 2; ++j) {
            int i   = tid + j * 256;
            int row = i >> 3;
            int q   = i & 7;
            uint32_t dst = smb + (uint32_t)((stg * STG + row * STRIDE + q * 4) * 4);
            const float* src = g_ent + (size_t)(mrow0 + row) * D_ + kc + q * 4;
            asm volatile("cp.async.cg.shared.global [%0], [%1], 16;"
                         :: "r"(dst), "l"(src) : "memory");
        }
        // B: 128 rows x 8 float4 = 1024
        #pragma unroll
        for (int j = 0; j < 4; ++j) {
            int i   = tid + j * 256;
            int row = i >> 3;
            int q   = i & 7;
            uint32_t dst = smb + (uint32_t)((stg * STG + A_SZ + row * STRIDE + q * 4) * 4);
            const float* src = fcw + (size_t)row * D_ + kc + q * 4;
            asm volatile("cp.async.cg.shared.global [%0], [%1], 16;"
                         :: "r"(dst), "l"(src) : "memory");
        }
        asm volatile("cp.async.commit_group;" ::: "memory");
    };

    issue(0, 0);

    #pragma unroll 1
    for (int it = 0; it < KCHUNK / KS; ++it) {
        int s = it & 1;
        asm volatile("cp.async.wait_group 0;" ::: "memory");
        __syncthreads();
        if (it + 1 < KCHUNK / KS) issue((it + 1) & 1, it + 1);

        uint32_t baseA = smb + (uint32_t)((s * STG) * 4);
        uint32_t baseB = smb + (uint32_t)((s * STG + A_SZ) * 4);

        #pragma unroll
        for (int ks = 0; ks < KS / 8; ++ks) {
            uint32_t aH[2][4], aL[2][4];
            #pragma unroll
            for (int f = 0; f < 2; ++f) {
                uint32_t aF[4];
                ldsm4(aF, baseA + (uint32_t)((aoff[f] + ks * 8) * 4));
                #pragma unroll
                for (int p = 0; p < 4; ++p) split2(aF[p], aH[f][p], aL[f][p]);
            }
            #pragma unroll
            for (int n2 = 0; n2 < 2; ++n2) {
                uint32_t bF[4], bH[4], bL[4];
                ldsm4(bF, baseB + (uint32_t)((boff[n2] + ks * 8) * 4));
                #pragma unroll
                for (int p = 0; p < 4; ++p) split2(bF[p], bH[p], bL[p]);
                #pragma unroll
                for (int f = 0; f < 2; ++f) {
                    mma8(acc[f][n2 * 2 + 0], aH[f], bH[0], bH[2]);
                    mma8(acc[f][n2 * 2 + 1], aH[f], bH[1], bH[3]);
                    mma8(acc[f][n2 * 2 + 0], aL[f], bH[0], bH[2]);
                    mma8(acc[f][n2 * 2 + 1], aL[f], bH[1], bH[3]);
                    mma8(acc[f][n2 * 2 + 0], aH[f], bL[0], bL[2]);
                    mma8(acc[f][n2 * 2 + 1], aH[f], bL[1], bL[3]);
                }
            }
        }
        __syncthreads();
    }

    // epilogue: write partials
    float* op = g_part + (size_t)split * (B_ * E_ * T_);
    #pragma unroll
    for (int f = 0; f < 2; ++f) {
        int r0 = mrow0 + mi * 32 + f * 16 + (lane >> 2);
        #pragma unroll
        for (int nt = 0; nt < 4; ++nt) {
            int c = ni * 32 + nt * 8 + (lane & 3) * 2;
            float2 v0 = make_float2(acc[f][nt][0], acc[f][nt][1]);
            float2 v1 = make_float2(acc[f][nt][2], acc[f][nt][3]);
            *(float2*)(op + (size_t)r0 * T_ + c)       = v0;
            *(float2*)(op + (size_t)(r0 + 8) * T_ + c) = v1;
        }
    }
}

// ---------------------------------------------------------------------------
// Kernel R: reduce 8 partials + bias -> out.
// ---------------------------------------------------------------------------
__global__ __launch_bounds__(256) void reduce_kernel(
    const float* __restrict__ bias, float* __restrict__ out)
{
    int i = blockIdx.x * 256 + threadIdx.x;   // 0 .. 262143
    float s = bias[i & (T_ - 1)];
    #pragma unroll
    for (int sp = 0; sp < KSPLIT; ++sp)
        s += g_part[(size_t)sp * (B_ * E_ * T_) + i];
    out[i] = s;
}

// ---------------------------------------------------------------------------
extern "C" void kernel_launch(void* const* d_in, const int* in_sizes, int n_in,
                              void* d_out, int out_size)
{
    const float* hs     = (const float*)d_in[0];
    const int*   idx    = (const int*)  d_in[1];
    const int*   counts = (const int*)  d_in[2];
    const int*   nent   = (const int*)  d_in[3];
    const float* fcw    = (const float*)d_in[4];
    const float* fcb    = (const float*)d_in[5];
    float*       out    = (float*)d_out;

    const int smem_bytes = 2 * STG * 4;   // 55296
    cudaFuncSetAttribute(mma_gemm, cudaFuncAttributeMaxDynamicSharedMemorySize,
                         smem_bytes);

    pool_kernel<<<B_ * E_, 256>>>(hs, idx, counts, nent);
    mma_gemm<<<dim3(B_ * E_ / 64, KSPLIT), 256, smem_bytes>>>(fcw);
    reduce_kernel<<<(B_ * E_ * T_) / 256, 256>>>(fcb, out);
}

// round 11
// speedup vs baseline: 2.5910x; 1.2003x over previous
#include <cuda_runtime.h>
#include <cuda_bf16.h>
#include <cstdint>

#define B_ 32
#define S_ 2048
#define D_ 1024
#define E_ 64
#define K_ 8
#define T_ 128       // N_TAGS
#define KSPLIT 8
#define KCHUNK 128   // K per split
#define KS 32        // k sub-chunk (bf16 elems) staged in smem
#define RSTR 40      // bf16 elems per smem row (80B: conflict-free, 16B aligned)
#define AH_OFF 0
#define AL_OFF (64 * RSTR)          // 2560
#define BH_OFF (2 * 64 * RSTR)      // 5120
#define BL_OFF (BH_OFF + 128 * RSTR) // 10240
#define STG_ELE (BL_OFF + 128 * RSTR) // 15360 bf16 = 30720 B per stage

// Scratch (allocation-free rule: __device__ globals)
__device__ __nv_bfloat16 g_eh[B_ * E_ * D_];     // 4 MB pooled, bf16-hi
__device__ __nv_bfloat16 g_el[B_ * E_ * D_];     // 4 MB pooled, bf16-lo
__device__ __nv_bfloat16 g_wh[T_ * D_];          // fc_w bf16-hi [T][D]
__device__ __nv_bfloat16 g_wl[T_ * D_];          // fc_w bf16-lo [T][D]
__device__ float g_part[KSPLIT * B_ * E_ * T_];  // 8 MB k-split partials

// ---- helpers ----------------------------------------------------------------
__device__ __forceinline__ uint32_t pack_hi_lo(float a, float b,
                                               float& ra, float& rb) {
    __nv_bfloat16 ha = __float2bfloat16_rn(a);
    __nv_bfloat16 hb = __float2bfloat16_rn(b);
    ra = a - __bfloat162float(ha);
    rb = b - __bfloat162float(hb);
    uint32_t r;
    uint16_t ua = *(uint16_t*)&ha, ub = *(uint16_t*)&hb;
    r = (uint32_t)ua | ((uint32_t)ub << 16);
    return r;
}
__device__ __forceinline__ uint32_t pack_bf2(float a, float b) {
    __nv_bfloat16 ha = __float2bfloat16_rn(a);
    __nv_bfloat16 hb = __float2bfloat16_rn(b);
    uint16_t ua = *(uint16_t*)&ha, ub = *(uint16_t*)&hb;
    return (uint32_t)ua | ((uint32_t)ub << 16);
}

__device__ __forceinline__ void ldsm4(uint32_t* r, uint32_t addr) {
    asm volatile("ldmatrix.sync.aligned.m8n8.x4.shared.b16 {%0,%1,%2,%3}, [%4];"
                 : "=r"(r[0]), "=r"(r[1]), "=r"(r[2]), "=r"(r[3]) : "r"(addr));
}
__device__ __forceinline__ void mma16(float* d, const uint32_t* a,
                                      uint32_t b0, uint32_t b1) {
    asm volatile(
        "mma.sync.aligned.m16n8k16.row.col.f32.bf16.bf16.f32 "
        "{%0,%1,%2,%3}, {%4,%5,%6,%7}, {%8,%9}, {%0,%1,%2,%3};"
        : "+f"(d[0]), "+f"(d[1]), "+f"(d[2]), "+f"(d[3])
        : "r"(a[0]), "r"(a[1]), "r"(a[2]), "r"(a[3]), "r"(b0), "r"(b1));
}
__device__ __forceinline__ void cp16(uint32_t dst, const void* src) {
    asm volatile("cp.async.cg.shared.global [%0], [%1], 16;"
                 :: "r"(dst), "l"(src) : "memory");
}

// ---------------------------------------------------------------------------
// Kernel P: gather + masked mean pool -> bf16 hi/lo split outputs.
// Blocks < 512 also split fc_w elementwise into g_wh/g_wl.
// ---------------------------------------------------------------------------
__global__ __launch_bounds__(256) void pool_kernel(
    const float* __restrict__ hs,      // [B,S,D]
    const int*   __restrict__ idx,     // [B,E,K]
    const int*   __restrict__ counts,  // [B,E]
    const int*   __restrict__ nent,    // [B]
    const float* __restrict__ W)       // fc_w [T,D]
{
    int be = blockIdx.x;           // 0..2047
    int b  = be >> 6;
    int e  = be & 63;
    int cnt = counts[be];
    bool active = (e < nent[b]);
    int t = threadIdx.x;

    float4 acc = make_float4(0.f, 0.f, 0.f, 0.f);
    if (active) {
        const float* base = hs + (size_t)b * (S_ * D_);
        #pragma unroll
        for (int k = 0; k < K_; ++k) {
            if (k < cnt) {
                int row = idx[be * K_ + k];
                float4 v = *(const float4*)(base + (size_t)row * D_ + t * 4);
                acc.x += v.x; acc.y += v.y; acc.z += v.z; acc.w += v.w;
            }
        }
        float inv = 1.0f / (float)cnt;
        acc.x *= inv; acc.y *= inv; acc.z *= inv; acc.w *= inv;
    }
    float rx, ry, rz, rw;
    uint2 hv, lv;
    hv.x = pack_hi_lo(acc.x, acc.y, rx, ry);
    hv.y = pack_hi_lo(acc.z, acc.w, rz, rw);
    lv.x = pack_bf2(rx, ry);
    lv.y = pack_bf2(rz, rw);
    *(uint2*)(g_eh + (size_t)be * D_ + t * 4) = hv;
    *(uint2*)(g_el + (size_t)be * D_ + t * 4) = lv;

    // fc_w hi/lo split: 512 blocks x 256 elements
    if (blockIdx.x < (T_ * D_) / 256) {
        int i = blockIdx.x * 256 + t;
        float w = W[i];
        __nv_bfloat16 wh = __float2bfloat16_rn(w);
        g_wh[i] = wh;
        g_wl[i] = __float2bfloat16_rn(w - __bfloat162float(wh));
    }
}

// ---------------------------------------------------------------------------
// Kernel B: bf16x3 split-K GEMM via mma.sync.m16n8k16 + ldmatrix + cp.async.
// grid = (32 m-tiles, 8 k-splits) = 256 CTAs (2/SM), 256 threads (8 warps).
// CTA tile: M64 x N128 x K128; warp tile m32 x n32; double-buffered k32.
// ---------------------------------------------------------------------------
__global__ __launch_bounds__(256, 2) void mma_gemm()
{
    extern __shared__ __nv_bfloat16 sm[];
    uint32_t smb;
    asm("{ .reg .u64 t; cvta.to.shared.u64 t, %1; cvt.u32.u64 %0, t; }"
        : "=r"(smb) : "l"(sm));

    int tid  = threadIdx.x;
    int lane = tid & 31;
    int warp = tid >> 5;
    int mi = warp >> 2;            // 0..1  -> m-sub (32 rows)
    int ni = warp & 3;             // 0..3  -> n-sub (32 cols)
    int mrow0 = blockIdx.x * 64;
    int split = blockIdx.y;
    int kbase = split * KCHUNK;

    // ldmatrix per-lane offsets (bf16 elems)
    int tile = lane >> 3;
    int tr   = lane & 7;
    int aoff[2], boff[2];
    #pragma unroll
    for (int f = 0; f < 2; ++f)
        aoff[f] = (mi * 32 + f * 16 + (tile & 1) * 8 + tr) * RSTR + (tile >> 1) * 8;
    #pragma unroll
    for (int n2 = 0; n2 < 2; ++n2)
        boff[n2] = (ni * 32 + n2 * 16 + (tile >> 1) * 8 + tr) * RSTR + (tile & 1) * 8;

    float acc[2][4][4];
    #pragma unroll
    for (int f = 0; f < 2; ++f)
        #pragma unroll
        for (int n = 0; n < 4; ++n)
            #pragma unroll
            for (int p = 0; p < 4; ++p) acc[f][n][p] = 0.f;

    auto issue = [&](int stg, int it) {
        int kc = kbase + it * KS;
        uint32_t sb = smb + (uint32_t)(stg * STG_ELE * 2);
        // A hi/lo: 64 rows x 4 segs(16B) = 256, one per thread
        {
            int row = tid >> 2, q = tid & 3;
            size_t g = (size_t)(mrow0 + row) * D_ + kc + q * 8;
            cp16(sb + (uint32_t)((AH_OFF + row * RSTR + q * 8) * 2), g_eh + g);
            cp16(sb + (uint32_t)((AL_OFF + row * RSTR + q * 8) * 2), g_el + g);
        }
        // B hi/lo: 128 rows x 4 segs = 512, two per thread
        #pragma unroll
        for (int j = 0; j < 2; ++j) {
            int i   = tid + j * 256;
            int row = i >> 2, q = i & 3;
            size_t g = (size_t)row * D_ + kc + q * 8;
            cp16(sb + (uint32_t)((BH_OFF + row * RSTR + q * 8) * 2), g_wh + g);
            cp16(sb + (uint32_t)((BL_OFF + row * RSTR + q * 8) * 2), g_wl + g);
        }
        asm volatile("cp.async.commit_group;" ::: "memory");
    };

    issue(0, 0);

    #pragma unroll 1
    for (int it = 0; it < KCHUNK / KS; ++it) {
        int s = it & 1;
        asm volatile("cp.async.wait_group 0;" ::: "memory");
        __syncthreads();
        if (it + 1 < KCHUNK / KS) issue((it + 1) & 1, it + 1);

        uint32_t sb = smb + (uint32_t)(s * STG_ELE * 2);

        #pragma unroll
        for (int ks = 0; ks < KS / 16; ++ks) {
            uint32_t aH[2][4], aL[2][4];
            #pragma unroll
            for (int f = 0; f < 2; ++f) {
                ldsm4(aH[f], sb + (uint32_t)((AH_OFF + aoff[f] + ks * 16) * 2));
                ldsm4(aL[f], sb + (uint32_t)((AL_OFF + aoff[f] + ks * 16) * 2));
            }
            #pragma unroll
            for (int n2 = 0; n2 < 2; ++n2) {
                uint32_t bH[4], bL[4];
                ldsm4(bH, sb + (uint32_t)((BH_OFF + boff[n2] + ks * 16) * 2));
                ldsm4(bL, sb + (uint32_t)((BL_OFF + boff[n2] + ks * 16) * 2));
                #pragma unroll
                for (int f = 0; f < 2; ++f) {
                    mma16(acc[f][n2 * 2 + 0], aH[f], bH[0], bH[1]);
                    mma16(acc[f][n2 * 2 + 1], aH[f], bH[2], bH[3]);
                    mma16(acc[f][n2 * 2 + 0], aL[f], bH[0], bH[1]);
                    mma16(acc[f][n2 * 2 + 1], aL[f], bH[2], bH[3]);
                    mma16(acc[f][n2 * 2 + 0], aH[f], bL[0], bL[1]);
                    mma16(acc[f][n2 * 2 + 1], aH[f], bL[2], bL[3]);
                }
            }
        }
        __syncthreads();
    }

    // epilogue: write partials
    float* op = g_part + (size_t)split * (B_ * E_ * T_);
    #pragma unroll
    for (int f = 0; f < 2; ++f) {
        int r0 = mrow0 + mi * 32 + f * 16 + (lane >> 2);
        #pragma unroll
        for (int nt = 0; nt < 4; ++nt) {
            int c = ni * 32 + nt * 8 + (lane & 3) * 2;
            float2 v0 = make_float2(acc[f][nt][0], acc[f][nt][1]);
            float2 v1 = make_float2(acc[f][nt][2], acc[f][nt][3]);
            *(float2*)(op + (size_t)r0 * T_ + c)       = v0;
            *(float2*)(op + (size_t)(r0 + 8) * T_ + c) = v1;
        }
    }
}

// ---------------------------------------------------------------------------
// Kernel R: reduce 8 partials + bias -> out.
// ---------------------------------------------------------------------------
__global__ __launch_bounds__(256) void reduce_kernel(
    const float* __restrict__ bias, float* __restrict__ out)
{
    int i = blockIdx.x * 256 + threadIdx.x;   // 0 .. 262143
    float s = bias[i & (T_ - 1)];
    #pragma unroll
    for (int sp = 0; sp < KSPLIT; ++sp)
        s += g_part[(size_t)sp * (B_ * E_ * T_) + i];
    out[i] = s;
}

// ---------------------------------------------------------------------------
extern "C" void kernel_launch(void* const* d_in, const int* in_sizes, int n_in,
                              void* d_out, int out_size)
{
    const float* hs     = (const float*)d_in[0];
    const int*   idx    = (const int*)  d_in[1];
    const int*   counts = (const int*)  d_in[2];
    const int*   nent   = (const int*)  d_in[3];
    const float* fcw    = (const float*)d_in[4];
    const float* fcb    = (const float*)d_in[5];
    float*       out    = (float*)d_out;

    const int smem_bytes = 2 * STG_ELE * 2;   // 61440
    cudaFuncSetAttribute(mma_gemm, cudaFuncAttributeMaxDynamicSharedMemorySize,
                         smem_bytes);

    pool_kernel<<<B_ * E_, 256>>>(hs, idx, counts, nent, fcw);
    mma_gemm<<<dim3(B_ * E_ / 64, KSPLIT), 256, smem_bytes>>>();
    reduce_kernel<<<(B_ * E_ * T_) / 256, 256>>>(fcb, out);
}

// round 12
// speedup vs baseline: 2.6261x; 1.0135x over previous
#include <cuda_runtime.h>
#include <cuda_bf16.h>
#include <cstdint>

#define B_ 32
#define S_ 2048
#define D_ 1024
#define E_ 64
#define K_ 8
#define T_ 128       // N_TAGS
#define KSPLIT 8
#define KCHUNK 128   // K per split
#define KS 32        // k sub-chunk (bf16 elems) staged in smem
#define RSTR 40      // bf16 elems per smem row (80B: conflict-free, 16B aligned)
#define AH_OFF 0
#define AL_OFF (64 * RSTR)          // 2560
#define BH_OFF (2 * 64 * RSTR)      // 5120
#define BL_OFF (BH_OFF + 128 * RSTR) // 10240
#define STG_ELE (BL_OFF + 128 * RSTR) // 15360 bf16 = 30720 B per stage

// Scratch (allocation-free rule: __device__ globals)
__device__ __nv_bfloat16 g_eh[B_ * E_ * D_];     // 4 MB pooled, bf16-hi
__device__ __nv_bfloat16 g_el[B_ * E_ * D_];     // 4 MB pooled, bf16-lo
__device__ __nv_bfloat16 g_wh[T_ * D_];          // fc_w bf16-hi [T][D]
__device__ __nv_bfloat16 g_wl[T_ * D_];          // fc_w bf16-lo [T][D]
__device__ float g_part[KSPLIT * B_ * E_ * T_];  // 8 MB k-split partials

// ---- helpers ----------------------------------------------------------------
__device__ __forceinline__ uint32_t pack_hi_lo(float a, float b,
                                               float& ra, float& rb) {
    __nv_bfloat16 ha = __float2bfloat16_rn(a);
    __nv_bfloat16 hb = __float2bfloat16_rn(b);
    ra = a - __bfloat162float(ha);
    rb = b - __bfloat162float(hb);
    uint16_t ua = *(uint16_t*)&ha, ub = *(uint16_t*)&hb;
    return (uint32_t)ua | ((uint32_t)ub << 16);
}
__device__ __forceinline__ uint32_t pack_bf2(float a, float b) {
    __nv_bfloat16 ha = __float2bfloat16_rn(a);
    __nv_bfloat16 hb = __float2bfloat16_rn(b);
    uint16_t ua = *(uint16_t*)&ha, ub = *(uint16_t*)&hb;
    return (uint32_t)ua | ((uint32_t)ub << 16);
}

__device__ __forceinline__ void ldsm4(uint32_t* r, uint32_t addr) {
    asm volatile("ldmatrix.sync.aligned.m8n8.x4.shared.b16 {%0,%1,%2,%3}, [%4];"
                 : "=r"(r[0]), "=r"(r[1]), "=r"(r[2]), "=r"(r[3]) : "r"(addr));
}
__device__ __forceinline__ void mma16(float* d, const uint32_t* a,
                                      uint32_t b0, uint32_t b1) {
    asm volatile(
        "mma.sync.aligned.m16n8k16.row.col.f32.bf16.bf16.f32 "
        "{%0,%1,%2,%3}, {%4,%5,%6,%7}, {%8,%9}, {%0,%1,%2,%3};"
        : "+f"(d[0]), "+f"(d[1]), "+f"(d[2]), "+f"(d[3])
        : "r"(a[0]), "r"(a[1]), "r"(a[2]), "r"(a[3]), "r"(b0), "r"(b1));
}
__device__ __forceinline__ void cp16(uint32_t dst, const void* src) {
    asm volatile("cp.async.cg.shared.global [%0], [%1], 16;"
                 :: "r"(dst), "l"(src) : "memory");
}

// ---------------------------------------------------------------------------
// Kernel P: gather + masked mean pool -> bf16 hi/lo split outputs.
// De-serialized gather: all 8 indices loaded up front (int4 x2), all 8 row
// loads issued unconditionally (clamped to row[0] for k>=cnt -> L1 hits),
// count mask applied as a post-multiply. Critical path: idx -> rows (2 levels).
// Blocks < 512 also split fc_w elementwise into g_wh/g_wl.
// ---------------------------------------------------------------------------
__global__ __launch_bounds__(256) void pool_kernel(
    const float* __restrict__ hs,      // [B,S,D]
    const int*   __restrict__ idx,     // [B,E,K]
    const int*   __restrict__ counts,  // [B,E]
    const int*   __restrict__ nent,    // [B]
    const float* __restrict__ W)       // fc_w [T,D]
{
    int be = blockIdx.x;           // 0..2047
    int b  = be >> 6;
    int e  = be & 63;
    int t  = threadIdx.x;

    // independent loads: issue all three streams up front
    int cnt    = counts[be];
    int ne     = nent[b];
    int4 ia    = *(const int4*)(idx + be * K_);
    int4 ib    = *(const int4*)(idx + be * K_ + 4);
    bool active = (e < ne);

    int r[8] = {ia.x, ia.y, ia.z, ia.w, ib.x, ib.y, ib.z, ib.w};
    #pragma unroll
    for (int k = 1; k < K_; ++k)
        r[k] = (k < cnt) ? r[k] : r[0];   // clamp -> dup loads hit L1

    float4 acc = make_float4(0.f, 0.f, 0.f, 0.f);
    if (active) {
        const float* base = hs + (size_t)b * (S_ * D_) + t * 4;
        float4 v[8];
        #pragma unroll
        for (int k = 0; k < K_; ++k)      // 8 unconditional batched LDG.128
            v[k] = *(const float4*)(base + (size_t)r[k] * D_);
        float inv = 1.0f / (float)cnt;
        #pragma unroll
        for (int k = 0; k < K_; ++k) {
            float w = (k < cnt) ? inv : 0.f;
            acc.x = fmaf(v[k].x, w, acc.x);
            acc.y = fmaf(v[k].y, w, acc.y);
            acc.z = fmaf(v[k].z, w, acc.z);
            acc.w = fmaf(v[k].w, w, acc.w);
        }
    }

    float rx, ry, rz, rw;
    uint2 hv, lv;
    hv.x = pack_hi_lo(acc.x, acc.y, rx, ry);
    hv.y = pack_hi_lo(acc.z, acc.w, rz, rw);
    lv.x = pack_bf2(rx, ry);
    lv.y = pack_bf2(rz, rw);
    *(uint2*)(g_eh + (size_t)be * D_ + t * 4) = hv;
    *(uint2*)(g_el + (size_t)be * D_ + t * 4) = lv;

    // fc_w hi/lo split: 512 blocks x 256 elements
    if (blockIdx.x < (T_ * D_) / 256) {
        int i = blockIdx.x * 256 + t;
        float w = W[i];
        __nv_bfloat16 wh = __float2bfloat16_rn(w);
        g_wh[i] = wh;
        g_wl[i] = __float2bfloat16_rn(w - __bfloat162float(wh));
    }
}

// ---------------------------------------------------------------------------
// Kernel B: bf16x3 split-K GEMM via mma.sync.m16n8k16 + ldmatrix + cp.async.
// grid = (32 m-tiles, 8 k-splits) = 256 CTAs (2/SM), 256 threads (8 warps).
// CTA tile: M64 x N128 x K128; warp tile m32 x n32; double-buffered k32.
// ---------------------------------------------------------------------------
__global__ __launch_bounds__(256, 2) void mma_gemm()
{
    extern __shared__ __nv_bfloat16 sm[];
    uint32_t smb;
    asm("{ .reg .u64 t; cvta.to.shared.u64 t, %1; cvt.u32.u64 %0, t; }"
        : "=r"(smb) : "l"(sm));

    int tid  = threadIdx.x;
    int lane = tid & 31;
    int warp = tid >> 5;
    int mi = warp >> 2;            // 0..1  -> m-sub (32 rows)
    int ni = warp & 3;             // 0..3  -> n-sub (32 cols)
    int mrow0 = blockIdx.x * 64;
    int split = blockIdx.y;
    int kbase = split * KCHUNK;

    // ldmatrix per-lane offsets (bf16 elems)
    int tile = lane >> 3;
    int tr   = lane & 7;
    int aoff[2], boff[2];
    #pragma unroll
    for (int f = 0; f < 2; ++f)
        aoff[f] = (mi * 32 + f * 16 + (tile & 1) * 8 + tr) * RSTR + (tile >> 1) * 8;
    #pragma unroll
    for (int n2 = 0; n2 < 2; ++n2)
        boff[n2] = (ni * 32 + n2 * 16 + (tile >> 1) * 8 + tr) * RSTR + (tile & 1) * 8;

    float acc[2][4][4];
    #pragma unroll
    for (int f = 0; f < 2; ++f)
        #pragma unroll
        for (int n = 0; n < 4; ++n)
            #pragma unroll
            for (int p = 0; p < 4; ++p) acc[f][n][p] = 0.f;

    auto issue = [&](int stg, int it) {
        int kc = kbase + it * KS;
        uint32_t sb = smb + (uint32_t)(stg * STG_ELE * 2);
        {
            int row = tid >> 2, q = tid & 3;
            size_t g = (size_t)(mrow0 + row) * D_ + kc + q * 8;
            cp16(sb + (uint32_t)((AH_OFF + row * RSTR + q * 8) * 2), g_eh + g);
            cp16(sb + (uint32_t)((AL_OFF + row * RSTR + q * 8) * 2), g_el + g);
        }
        #pragma unroll
        for (int j = 0; j < 2; ++j) {
            int i   = tid + j * 256;
            int row = i >> 2, q = i & 3;
            size_t g = (size_t)row * D_ + kc + q * 8;
            cp16(sb + (uint32_t)((BH_OFF + row * RSTR + q * 8) * 2), g_wh + g);
            cp16(sb + (uint32_t)((BL_OFF + row * RSTR + q * 8) * 2), g_wl + g);
        }
        asm volatile("cp.async.commit_group;" ::: "memory");
    };

    issue(0, 0);

    #pragma unroll 1
    for (int it = 0; it < KCHUNK / KS; ++it) {
        int s = it & 1;
        asm volatile("cp.async.wait_group 0;" ::: "memory");
        __syncthreads();
        if (it + 1 < KCHUNK / KS) issue((it + 1) & 1, it + 1);

        uint32_t sb = smb + (uint32_t)(s * STG_ELE * 2);

        #pragma unroll
        for (int ks = 0; ks < KS / 16; ++ks) {
            uint32_t aH[2][4], aL[2][4];
            #pragma unroll
            for (int f = 0; f < 2; ++f) {
                ldsm4(aH[f], sb + (uint32_t)((AH_OFF + aoff[f] + ks * 16) * 2));
                ldsm4(aL[f], sb + (uint32_t)((AL_OFF + aoff[f] + ks * 16) * 2));
            }
            #pragma unroll
            for (int n2 = 0; n2 < 2; ++n2) {
                uint32_t bH[4], bL[4];
                ldsm4(bH, sb + (uint32_t)((BH_OFF + boff[n2] + ks * 16) * 2));
                ldsm4(bL, sb + (uint32_t)((BL_OFF + boff[n2] + ks * 16) * 2));
                #pragma unroll
                for (int f = 0; f < 2; ++f) {
                    mma16(acc[f][n2 * 2 + 0], aH[f], bH[0], bH[1]);
                    mma16(acc[f][n2 * 2 + 1], aH[f], bH[2], bH[3]);
                    mma16(acc[f][n2 * 2 + 0], aL[f], bH[0], bH[1]);
                    mma16(acc[f][n2 * 2 + 1], aL[f], bH[2], bH[3]);
                    mma16(acc[f][n2 * 2 + 0], aH[f], bL[0], bL[1]);
                    mma16(acc[f][n2 * 2 + 1], aH[f], bL[2], bL[3]);
                }
            }
        }
        __syncthreads();
    }

    // epilogue: write partials
    float* op = g_part + (size_t)split * (B_ * E_ * T_);
    #pragma unroll
    for (int f = 0; f < 2; ++f) {
        int r0 = mrow0 + mi * 32 + f * 16 + (lane >> 2);
        #pragma unroll
        for (int nt = 0; nt < 4; ++nt) {
            int c = ni * 32 + nt * 8 + (lane & 3) * 2;
            float2 v0 = make_float2(acc[f][nt][0], acc[f][nt][1]);
            float2 v1 = make_float2(acc[f][nt][2], acc[f][nt][3]);
            *(float2*)(op + (size_t)r0 * T_ + c)       = v0;
            *(float2*)(op + (size_t)(r0 + 8) * T_ + c) = v1;
        }
    }
}

// ---------------------------------------------------------------------------
// Kernel R: reduce 8 partials + bias -> out.
// ---------------------------------------------------------------------------
__global__ __launch_bounds__(256) void reduce_kernel(
    const float* __restrict__ bias, float* __restrict__ out)
{
    int i = blockIdx.x * 256 + threadIdx.x;   // 0 .. 262143
    float s = bias[i & (T_ - 1)];
    #pragma unroll
    for (int sp = 0; sp < KSPLIT; ++sp)
        s += g_part[(size_t)sp * (B_ * E_ * T_) + i];
    out[i] = s;
}

// ---------------------------------------------------------------------------
extern "C" void kernel_launch(void* const* d_in, const int* in_sizes, int n_in,
                              void* d_out, int out_size)
{
    const float* hs     = (const float*)d_in[0];
    const int*   idx    = (const int*)  d_in[1];
    const int*   counts = (const int*)  d_in[2];
    const int*   nent   = (const int*)  d_in[3];
    const float* fcw    = (const float*)d_in[4];
    const float* fcb    = (const float*)d_in[5];
    float*       out    = (float*)d_out;

    const int smem_bytes = 2 * STG_ELE * 2;   // 61440
    cudaFuncSetAttribute(mma_gemm, cudaFuncAttributeMaxDynamicSharedMemorySize,
                         smem_bytes);

    pool_kernel<<<B_ * E_, 256>>>(hs, idx, counts, nent, fcw);
    mma_gemm<<<dim3(B_ * E_ / 64, KSPLIT), 256, smem_bytes>>>();
    reduce_kernel<<<(B_ * E_ * T_) / 256, 256>>>(fcb, out);
}